// round 12
// baseline (speedup 1.0000x reference)
#include <cuda_runtime.h>
#include <cuda_fp16.h>
#include <math.h>
#include <stdint.h>

// Problem constants
#define Bb 2
#define Ss 4096
#define Dd 1024
#define Hh 16
#define HDh 64
#define Rr 16
#define Mm (Bb*Ss)            // 8192 rows

// ---------------- device scratch (all fp16) ------------------------------------------
__device__ __half g_Wq[Dd*Dd];
__device__ __half g_Wk[Dd*Dd];
__device__ __half g_Wv[Dd*Dd];
__device__ __half g_Wo[Dd*Dd];
__device__ __half g_X [(size_t)Mm*Dd];
__device__ __half g_Qh[(size_t)Mm*Dd];
__device__ __half g_Kh[(size_t)Mm*Dd];
__device__ __half g_Vt[(size_t)Mm*Dd];        // [b*16+h][64][4096] transposed V (fp16)
__device__ __half g_AO[(size_t)Mm*Dd];

#define CP16(dst, src) asm volatile("cp.async.cg.shared.global [%0], [%1], 16;" :: "r"(dst), "l"(src))

__device__ __forceinline__ uint32_t h2u(__half2 h) { return *(uint32_t*)&h; }
__device__ __forceinline__ float ex2f(float x) {
    float y; asm("ex2.approx.f32 %0, %1;" : "=f"(y) : "f"(x)); return y;
}

#define MMA_F16(d, a, b0, b1) \
    asm volatile("mma.sync.aligned.m16n8k16.row.col.f32.f16.f16.f32 " \
        "{%0,%1,%2,%3}, {%4,%5,%6,%7}, {%8,%9}, {%0,%1,%2,%3};" \
        : "+f"(d[0]), "+f"(d[1]), "+f"(d[2]), "+f"(d[3]) \
        : "r"(a[0]), "r"(a[1]), "r"(a[2]), "r"(a[3]), "r"(b0), "r"(b1))

#define LDSM4(r0, r1, r2, r3, addr) \
    asm volatile("ldmatrix.sync.aligned.m8n8.x4.shared.b16 {%0,%1,%2,%3}, [%4];" \
        : "=r"(r0), "=r"(r1), "=r"(r2), "=r"(r3) : "r"(addr))

#define GBAR(id) asm volatile("bar.sync %0, 128;" :: "r"(id) : "memory")

// ---------------- W_eff = fp16( W + l2 @ l1 ), all 4 weights in one launch ----------
struct WeffArgs {
    const float* w[4]; const float* l1[4]; const float* l2[4]; __half* out[4];
};
__global__ void build_weff4_kernel(WeffArgs a) {
    int wi  = blockIdx.x >> 12;
    int idx = ((blockIdx.x & 4095) << 8) + threadIdx.x;
    int n = idx >> 10, k = idx & 1023;
    const float* l1 = a.l1[wi];
    const float* l2 = a.l2[wi];
    float acc = a.w[wi][idx];
#pragma unroll
    for (int r = 0; r < Rr; r++) acc += l2[n*Rr + r] * l1[r*Dd + k];
    a.out[wi][idx] = __float2half(acc);
}

__global__ void round_x_kernel(const float4* __restrict__ in, uint2* __restrict__ out) {
    int i = blockIdx.x * blockDim.x + threadIdx.x;
    float4 v = in[i];
    out[i] = make_uint2(h2u(__floats2half2_rn(v.x, v.y)), h2u(__floats2half2_rn(v.z, v.w)));
}

// ---------------- GEMM tiling constants ----------------------------------------------
#define BM 128
#define BN 128
#define HBK 64
#define ROWB 144
#define HSTG (2*BM*ROWB)
#define GSTAGES 3
#define GEMM_SMEM (GSTAGES*HSTG)
#define NCH (Dd/HBK)
#define SCALE_Q 0.18033688011112042f      // 0.125 * log2(e)

#define HLOAD(CH, Ap, Wp) do {                                              \
        uint32_t _stg = sm_sh + (uint32_t)((CH) % GSTAGES) * HSTG;          \
        _Pragma("unroll")                                                   \
        for (int _j = 0; _j < 4; _j++) {                                    \
            int _cl = tid + 256*_j;                                         \
            int _row = _cl >> 3, _seg = _cl & 7;                            \
            uint32_t _off = (uint32_t)(_row*ROWB + _seg*16);                \
            CP16(_stg + _off,            (Ap) + (size_t)(bm + _row)*Dd + (CH)*HBK + _seg*8); \
            CP16(_stg + BM*ROWB + _off,  (Wp) + (size_t)(bn + _row)*Dd + (CH)*HBK + _seg*8); \
        }                                                                   \
        asm volatile("cp.async.commit_group;");                             \
    } while (0)

#define GEMM_MAINLOOP(Ap, Wp)                                               \
    HLOAD(0, Ap, Wp);                                                       \
    HLOAD(1, Ap, Wp);                                                       \
    for (int it = 0; it < NCH; it++) {                                      \
        if (it + 1 < NCH) asm volatile("cp.async.wait_group 1;");           \
        else              asm volatile("cp.async.wait_group 0;");           \
        __syncthreads();                                                    \
        if (it + 2 < NCH) HLOAD(it + 2, Ap, Wp);                            \
        uint32_t stg = sm_sh + (uint32_t)(it % GSTAGES) * HSTG;             \
        uint32_t aA = stg + (uint32_t)wm*ROWB + laneoff;                    \
        uint32_t aB = stg + BM*ROWB + (uint32_t)wn*ROWB + laneoff;          \
        _Pragma("unroll")                                                   \
        for (int kk = 0; kk < 4; kk++) {                                    \
            uint32_t af[2][4], bf[8][2];                                    \
            LDSM4(af[0][0], af[0][1], af[0][2], af[0][3], aA + kk*32);      \
            LDSM4(af[1][0], af[1][1], af[1][2], af[1][3], aA + 16*ROWB + kk*32); \
            _Pragma("unroll")                                               \
            for (int p = 0; p < 4; p++) {                                   \
                uint32_t r0, r1, r2, r3;                                    \
                LDSM4(r0, r1, r2, r3, aB + p*16*ROWB + kk*32);              \
                bf[2*p][0] = r0; bf[2*p+1][0] = r1;                         \
                bf[2*p][1] = r2; bf[2*p+1][1] = r3;                         \
            }                                                               \
            _Pragma("unroll")                                               \
            for (int mi = 0; mi < 2; mi++)                                  \
                _Pragma("unroll")                                           \
                for (int ni = 0; ni < 8; ni++)                              \
                    MMA_F16(acc[mi][ni], af[mi], bf[ni][0], bf[ni][1]);     \
        }                                                                   \
    }

// ---------------- merged Q/K/V projection kernel (blockIdx.z selects) ----------------
__global__ __launch_bounds__(256) void qkv_gemm_kernel(
    const __half* __restrict__ X,
    const __half* __restrict__ Wq, const __half* __restrict__ Wk, const __half* __restrict__ Wv,
    const float* __restrict__ wqb,
    __half* __restrict__ Qh, __half* __restrict__ Kh, __half* __restrict__ Vt,
    const float* __restrict__ fc, const float* __restrict__ fs)
{
    extern __shared__ char smc[];
    uint32_t sm_sh;
    asm("{ .reg .u64 t; cvta.to.shared.u64 t, %1; cvt.u32.u64 %0, t; }" : "=r"(sm_sh) : "l"(smc));

    const int tid  = threadIdx.x;
    const int bm   = blockIdx.y * BM;
    const int bn   = blockIdx.x * BN;
    const int z    = blockIdx.z;              // 0=Q, 1=K, 2=V
    const int warp = tid >> 5, lane = tid & 31;
    const int g = lane >> 2;
    const int q = lane & 3;
    const int wm = (warp >> 1) * 32;
    const int wn = (warp & 1) * 64;
    const uint32_t laneoff = (uint32_t)((lane & 15) * ROWB + ((lane >> 4) << 4));

    const __half* W = (z == 0) ? Wq : (z == 1) ? Wk : Wv;
    float acc[2][8][4] = {};

    GEMM_MAINLOOP(X, W)

    if (z < 2) {          // Q or K: RoPE (+bias,+scale for Q) -> fp16
#pragma unroll
        for (int mi = 0; mi < 2; mi++) {
            int r0 = bm + wm + mi*16 + g;
            int s0 = r0 & (Ss-1), s1 = (r0+8) & (Ss-1);
            __half* Ph = (z == 0) ? Qh : Kh;
#pragma unroll
            for (int ni = 0; ni < 8; ni++) {
                int cn = bn + wn + ni*8 + q*2;
                int p = (cn & 63) >> 1;
                float b0 = 0.f, b1 = 0.f;
                if (z == 0) { b0 = wqb[cn]; b1 = wqb[cn+1]; }
                float c0 = fc[s0*32+p], n0 = fs[s0*32+p];
                float c1 = fc[s1*32+p], n1 = fs[s1*32+p];
                float e0 = acc[mi][ni][0]+b0, o0 = acc[mi][ni][1]+b1;
                float e1 = acc[mi][ni][2]+b0, o1 = acc[mi][ni][3]+b1;
                float re0 = e0*c0 - o0*n0, im0 = e0*n0 + o0*c0;
                float re1 = e1*c1 - o1*n1, im1 = e1*n1 + o1*c1;
                if (z == 0) { re0 *= SCALE_Q; im0 *= SCALE_Q; re1 *= SCALE_Q; im1 *= SCALE_Q; }
                *(__half2*)&Ph[(size_t)r0    *Dd + cn] = __floats2half2_rn(re0, im0);
                *(__half2*)&Ph[(size_t)(r0+8)*Dd + cn] = __floats2half2_rn(re1, im1);
            }
        }
    } else {              // V: transposed fp16
#pragma unroll
        for (int mi = 0; mi < 2; mi++) {
            int r0 = bm + wm + mi*16 + g;
            int sl = r0 & (Ss-1);
            size_t bb = (size_t)(r0 >> 12);
#pragma unroll
            for (int ni = 0; ni < 8; ni++) {
                int cn = bn + wn + ni*8 + q*2;
                int hh = cn >> 6, dd = cn & 63;
                size_t vb = ((bb*Hh + hh)*HDh + dd) * (size_t)Ss;
                Vt[vb      + sl    ] = __float2half(acc[mi][ni][0]);
                Vt[vb + Ss + sl    ] = __float2half(acc[mi][ni][1]);
                Vt[vb      + sl + 8] = __float2half(acc[mi][ni][2]);
                Vt[vb + Ss + sl + 8] = __float2half(acc[mi][ni][3]);
            }
        }
    }
}

// ---------------- output projection kernel (fp32 + bias into d_out) ------------------
__global__ __launch_bounds__(256) void oproj_gemm_kernel(
    const __half* __restrict__ A, const __half* __restrict__ W,
    const float* __restrict__ bias, float* __restrict__ C)
{
    extern __shared__ char smc[];
    uint32_t sm_sh;
    asm("{ .reg .u64 t; cvta.to.shared.u64 t, %1; cvt.u32.u64 %0, t; }" : "=r"(sm_sh) : "l"(smc));

    const int tid  = threadIdx.x;
    const int bm   = blockIdx.y * BM;
    const int bn   = blockIdx.x * BN;
    const int warp = tid >> 5, lane = tid & 31;
    const int g = lane >> 2;
    const int q = lane & 3;
    const int wm = (warp >> 1) * 32;
    const int wn = (warp & 1) * 64;
    const uint32_t laneoff = (uint32_t)((lane & 15) * ROWB + ((lane >> 4) << 4));

    float acc[2][8][4] = {};

    GEMM_MAINLOOP(A, W)

#pragma unroll
    for (int mi = 0; mi < 2; mi++) {
        int r0 = bm + wm + mi*16 + g;
#pragma unroll
        for (int ni = 0; ni < 8; ni++) {
            int cn = bn + wn + ni*8 + q*2;
            float b0 = bias[cn], b1 = bias[cn+1];
            *(float2*)&C[(size_t)r0     *Dd + cn] = make_float2(acc[mi][ni][0]+b0, acc[mi][ni][1]+b1);
            *(float2*)&C[(size_t)(r0+8) *Dd + cn] = make_float2(acc[mi][ni][2]+b0, acc[mi][ni][3]+b1);
        }
    }
}

// ---------------- FP16 flash attention: 2 independent warpgroups per CTA -------------
// Each 128-thread warpgroup owns one 64-row q-tile, its own 2-stage K/V smem
// pipeline, its own cp.async stream, and a private named barrier. CTA pairs
// q-tiles (w, 63-w) -> exactly 65 iterations per CTA (perfect causal balance).
#define AQ2 64
#define KVB 9216                          // one 64x64-half plane (144B rows)
#define GSTG (2*KVB)                      // K + V per stage = 18432
#define GRP_BYTES (2*GSTG + AQ2*ROWB)     // 2 stages + Q staging = 46080
#define ATTN_SMEM (2*GRP_BYTES)           // 92160

__global__ __launch_bounds__(256) void attn_mma_kernel(
    const __half* __restrict__ Qh, const __half* __restrict__ Kh,
    const __half* __restrict__ Vt, __half* __restrict__ O)
{
    extern __shared__ char smc[];
    uint32_t sm_sh;
    asm("{ .reg .u64 t; cvta.to.shared.u64 t, %1; cvt.u32.u64 %0, t; }" : "=r"(sm_sh) : "l"(smc));

    const int tid  = threadIdx.x;
    const int wg   = tid >> 7;               // warpgroup 0/1
    const int wtid = tid & 127;
    const int warp = wtid >> 5, lane = tid & 31;
    const int g = lane >> 2, q = lane & 3;
    const int barid = wg + 1;
    const int qt = wg ? (63 - blockIdx.x) : blockIdx.x;   // 64-row q-tile index
    const int bh = blockIdx.y;
    const int b = bh >> 4, h = bh & 15;
    const size_t headoff = (size_t)b * Ss * Dd + (size_t)h * HDh;
    const size_t vhead = (size_t)bh * HDh * Ss;
    const int w16 = warp * 16;
    const uint32_t grp = sm_sh + (uint32_t)wg * GRP_BYTES;
    const uint32_t laneoff = (uint32_t)((lane & 15) * ROWB + ((lane >> 4) << 4));

    // ---- stage this group's Q (64 rows) into its smem region ----
    {
        const int r = wtid >> 1, half = wtid & 1;
        const __half* src = Qh + headoff + (size_t)(qt*AQ2 + r)*Dd + half*32;
        uint4* dst = (uint4*)(smc + wg*GRP_BYTES + 2*GSTG + r*ROWB + half*64);
#pragma unroll
        for (int i = 0; i < 4; i++) dst[i] = ((const uint4*)src)[i];
    }
    GBAR(barid);

    uint32_t aQ[4][4];
    {
        uint32_t qb = grp + 2*GSTG + (uint32_t)w16*ROWB + laneoff;
#pragma unroll
        for (int s = 0; s < 4; s++)
            LDSM4(aQ[s][0], aQ[s][1], aQ[s][2], aQ[s][3], qb + s*32);
    }

#define APREFETCH(KT) do {                                                          \
        uint32_t _stg = grp + (uint32_t)((KT) & 1) * GSTG;                          \
        int _pl = wtid >> 6;                /* 0: K plane, 1: V plane */            \
        int _r = wtid & 63;                                                         \
        const __half* _gs;                                                          \
        if (_pl == 0) _gs = Kh + headoff + (size_t)((KT)*AQ2 + _r)*Dd;              \
        else          _gs = Vt + vhead + (size_t)_r*Ss + (KT)*AQ2;                  \
        uint32_t _dst = _stg + (_pl ? KVB : 0) + (uint32_t)(_r*ROWB);               \
        _Pragma("unroll")                                                           \
        for (int _i = 0; _i < 8; _i++)                                              \
            CP16(_dst + _i*16, (const char*)_gs + _i*16);                           \
        asm volatile("cp.async.commit_group;");                                     \
    } while (0)

    float accO[8][4] = {};
    float m0 = -1e30f, m1 = -1e30f, l0 = 0.f, l1 = 0.f;
    const int nkt = qt + 1;

    APREFETCH(0);

    for (int kt = 0; kt < nkt; kt++) {
        asm volatile("cp.async.wait_group 0;");
        GBAR(barid);                       // kt data visible; kt-1 compute done
        if (kt + 1 < nkt) APREFETCH(kt + 1);

        uint32_t aK = grp + (uint32_t)(kt & 1) * GSTG + laneoff;
        uint32_t aV = aK + KVB;

        // S = q @ k^T  (Q pre-scaled by 0.125*log2e -> S in log2 domain)
        float S[8][4] = {};
#pragma unroll
        for (int s = 0; s < 4; s++) {
            uint32_t bk[8][2];
#pragma unroll
            for (int p = 0; p < 4; p++) {
                uint32_t r0, r1, r2, r3;
                LDSM4(r0, r1, r2, r3, aK + p*16*ROWB + s*32);
                bk[2*p][0] = r0; bk[2*p+1][0] = r1; bk[2*p][1] = r2; bk[2*p+1][1] = r3;
            }
#pragma unroll
            for (int ni = 0; ni < 8; ni++)
                MMA_F16(S[ni], aQ[s], bk[ni][0], bk[ni][1]);
        }

        // hoist V fragments for s=0 — drains during softmax
        uint32_t bv0[8][2];
#pragma unroll
        for (int p = 0; p < 4; p++) {
            uint32_t r0, r1, r2, r3;
            LDSM4(r0, r1, r2, r3, aV + p*16*ROWB);
            bv0[2*p][0] = r0; bv0[2*p+1][0] = r1; bv0[2*p][1] = r2; bv0[2*p+1][1] = r3;
        }

        // causal mask (only the diagonal tile)
        if (kt == qt) {
            const int r0g = w16 + g, r1g = r0g + 8;   // row within tile == col space
#pragma unroll
            for (int ni = 0; ni < 8; ni++) {
                int c = ni*8 + 2*q;
                if (c     > r0g) S[ni][0] = -1e30f;
                if (c + 1 > r0g) S[ni][1] = -1e30f;
                if (c     > r1g) S[ni][2] = -1e30f;
                if (c + 1 > r1g) S[ni][3] = -1e30f;
            }
        }

        // online softmax in log2 domain (l kept as per-lane partials)
        float mx0 = -1e30f, mx1 = -1e30f;
#pragma unroll
        for (int ni = 0; ni < 8; ni++) {
            mx0 = fmaxf(mx0, fmaxf(S[ni][0], S[ni][1]));
            mx1 = fmaxf(mx1, fmaxf(S[ni][2], S[ni][3]));
        }
        mx0 = fmaxf(mx0, __shfl_xor_sync(0xffffffffu, mx0, 1));
        mx0 = fmaxf(mx0, __shfl_xor_sync(0xffffffffu, mx0, 2));
        mx1 = fmaxf(mx1, __shfl_xor_sync(0xffffffffu, mx1, 1));
        mx1 = fmaxf(mx1, __shfl_xor_sync(0xffffffffu, mx1, 2));
        float mn0 = fmaxf(m0, mx0), mn1 = fmaxf(m1, mx1);
        if (__any_sync(0xffffffffu, (mn0 > m0) || (mn1 > m1))) {
            float cr0 = ex2f(m0 - mn0), cr1 = ex2f(m1 - mn1);
            m0 = mn0; m1 = mn1;
            l0 *= cr0; l1 *= cr1;
#pragma unroll
            for (int ni = 0; ni < 8; ni++) {
                accO[ni][0] *= cr0; accO[ni][1] *= cr0;
                accO[ni][2] *= cr1; accO[ni][3] *= cr1;
            }
        }
#pragma unroll
        for (int ni = 0; ni < 8; ni++) {
            S[ni][0] = ex2f(S[ni][0] - m0);
            S[ni][1] = ex2f(S[ni][1] - m0);
            S[ni][2] = ex2f(S[ni][2] - m1);
            S[ni][3] = ex2f(S[ni][3] - m1);
            l0 += S[ni][0] + S[ni][1];
            l1 += S[ni][2] + S[ni][3];
        }

        // O += P @ V  — P taken directly from S registers (C-frag == A-frag layout)
#pragma unroll
        for (int s = 0; s < 4; s++) {
            uint32_t ap[4];
            ap[0] = h2u(__floats2half2_rn(S[2*s  ][0], S[2*s  ][1]));
            ap[1] = h2u(__floats2half2_rn(S[2*s  ][2], S[2*s  ][3]));
            ap[2] = h2u(__floats2half2_rn(S[2*s+1][0], S[2*s+1][1]));
            ap[3] = h2u(__floats2half2_rn(S[2*s+1][2], S[2*s+1][3]));
            if (s == 0) {
#pragma unroll
                for (int ni = 0; ni < 8; ni++)
                    MMA_F16(accO[ni], ap, bv0[ni][0], bv0[ni][1]);
            } else {
                uint32_t bv[8][2];
#pragma unroll
                for (int p = 0; p < 4; p++) {
                    uint32_t r0, r1, r2, r3;
                    LDSM4(r0, r1, r2, r3, aV + p*16*ROWB + s*32);
                    bv[2*p][0] = r0; bv[2*p+1][0] = r1; bv[2*p][1] = r2; bv[2*p+1][1] = r3;
                }
#pragma unroll
                for (int ni = 0; ni < 8; ni++)
                    MMA_F16(accO[ni], ap, bv[ni][0], bv[ni][1]);
            }
        }
    }
#undef APREFETCH

    // epilogue: reduce l partials across the quad, normalize, store fp16
    l0 += __shfl_xor_sync(0xffffffffu, l0, 1);
    l0 += __shfl_xor_sync(0xffffffffu, l0, 2);
    l1 += __shfl_xor_sync(0xffffffffu, l1, 1);
    l1 += __shfl_xor_sync(0xffffffffu, l1, 2);
    float inv0 = 1.f / l0, inv1 = 1.f / l1;
    size_t base0 = headoff + (size_t)(qt*AQ2 + w16 + g) * Dd;
    size_t base1 = base0 + (size_t)8 * Dd;
#pragma unroll
    for (int ni = 0; ni < 8; ni++) {
        int c = ni*8 + 2*q;
        *(__half2*)&O[base0 + c] = __floats2half2_rn(accO[ni][0]*inv0, accO[ni][1]*inv0);
        *(__half2*)&O[base1 + c] = __floats2half2_rn(accO[ni][2]*inv1, accO[ni][3]*inv1);
    }
}

// ---------------- launch -------------------------------------------------------------
extern "C" void kernel_launch(void* const* d_in, const int* in_sizes, int n_in,
                              void* d_out, int out_size) {
    const float* x   = (const float*)d_in[0];
    const float* fc  = (const float*)d_in[1];
    const float* fs  = (const float*)d_in[2];
    const float* wq  = (const float*)d_in[4];
    const float* wqb = (const float*)d_in[5];
    const float* wk  = (const float*)d_in[6];
    const float* wv  = (const float*)d_in[7];
    const float* wo  = (const float*)d_in[8];
    const float* wob = (const float*)d_in[9];

    __half *Wq, *Wk, *Wv, *Wo, *Xr, *Qhp, *Khp, *Vtp, *AO;
    cudaGetSymbolAddress((void**)&Wq, g_Wq);
    cudaGetSymbolAddress((void**)&Wk, g_Wk);
    cudaGetSymbolAddress((void**)&Wv, g_Wv);
    cudaGetSymbolAddress((void**)&Wo, g_Wo);
    cudaGetSymbolAddress((void**)&Xr, g_X);
    cudaGetSymbolAddress((void**)&Qhp, g_Qh);
    cudaGetSymbolAddress((void**)&Khp, g_Kh);
    cudaGetSymbolAddress((void**)&Vtp, g_Vt);
    cudaGetSymbolAddress((void**)&AO, g_AO);

    cudaFuncSetAttribute(qkv_gemm_kernel, cudaFuncAttributeMaxDynamicSharedMemorySize, GEMM_SMEM);
    cudaFuncSetAttribute(oproj_gemm_kernel, cudaFuncAttributeMaxDynamicSharedMemorySize, GEMM_SMEM);
    cudaFuncSetAttribute(attn_mma_kernel, cudaFuncAttributeMaxDynamicSharedMemorySize, ATTN_SMEM);

    // 1. Fold LoRA into the 4 effective weights (fp16); round x to fp16
    WeffArgs wa;
    wa.w[0]=wq; wa.l1[0]=(const float*)d_in[10]; wa.l2[0]=(const float*)d_in[11]; wa.out[0]=Wq;
    wa.w[1]=wk; wa.l1[1]=(const float*)d_in[12]; wa.l2[1]=(const float*)d_in[13]; wa.out[1]=Wk;
    wa.w[2]=wv; wa.l1[2]=(const float*)d_in[14]; wa.l2[2]=(const float*)d_in[15]; wa.out[2]=Wv;
    wa.w[3]=wo; wa.l1[3]=(const float*)d_in[16]; wa.l2[3]=(const float*)d_in[17]; wa.out[3]=Wo;
    build_weff4_kernel<<<4*4096, 256>>>(wa);
    round_x_kernel<<<(Mm*Dd/4)/256, 256>>>((const float4*)x, (uint2*)Xr);

    // 2. Q/K/V projections in ONE launch (z selects weight + epilogue)
    dim3 gq(Dd/BN, Mm/BM, 3);
    qkv_gemm_kernel<<<gq, 256, GEMM_SMEM>>>(Xr, Wq, Wk, Wv, wqb, Qhp, Khp, Vtp, fc, fs);

    // 3. FP16 flash attention — paired 64-row q-tiles, independent warpgroups
    dim3 ga(Ss/(2*AQ2), Bb*Hh);            // 32 tile-pairs x 32 heads
    attn_mma_kernel<<<ga, 256, ATTN_SMEM>>>(Qhp, Khp, Vtp, AO);

    // 4. Output projection into d_out (fp32 + bias)
    dim3 gg(Dd/BN, Mm/BM);
    oproj_gemm_kernel<<<gg, 256, GEMM_SMEM>>>(AO, Wo, wob, (float*)d_out);
}

// round 14
// speedup vs baseline: 1.2284x; 1.2284x over previous
#include <cuda_runtime.h>
#include <cuda_fp16.h>
#include <math.h>
#include <stdint.h>

// Problem constants
#define Bb 2
#define Ss 4096
#define Dd 1024
#define Hh 16
#define HDh 64
#define Rr 16
#define Mm (Bb*Ss)            // 8192 rows

// ---------------- device scratch (all fp16) ------------------------------------------
__device__ __half g_Wq[Dd*Dd];
__device__ __half g_Wk[Dd*Dd];
__device__ __half g_Wv[Dd*Dd];
__device__ __half g_Wo[Dd*Dd];
__device__ __half g_X [(size_t)Mm*Dd];
__device__ __half g_Qh[(size_t)Mm*Dd];
__device__ __half g_Kh[(size_t)Mm*Dd];
__device__ __half g_Vt[(size_t)Mm*Dd];        // [b*16+h][64][4096] transposed V (fp16)
__device__ __half g_AO[(size_t)Mm*Dd];

#define CP16(dst, src) asm volatile("cp.async.cg.shared.global [%0], [%1], 16;" :: "r"(dst), "l"(src))

__device__ __forceinline__ uint32_t h2u(__half2 h) { return *(uint32_t*)&h; }
__device__ __forceinline__ float ex2f(float x) {
    float y; asm("ex2.approx.f32 %0, %1;" : "=f"(y) : "f"(x)); return y;
}

#define MMA_F16(d, a, b0, b1) \
    asm volatile("mma.sync.aligned.m16n8k16.row.col.f32.f16.f16.f32 " \
        "{%0,%1,%2,%3}, {%4,%5,%6,%7}, {%8,%9}, {%0,%1,%2,%3};" \
        : "+f"(d[0]), "+f"(d[1]), "+f"(d[2]), "+f"(d[3]) \
        : "r"(a[0]), "r"(a[1]), "r"(a[2]), "r"(a[3]), "r"(b0), "r"(b1))

#define LDSM4(r0, r1, r2, r3, addr) \
    asm volatile("ldmatrix.sync.aligned.m8n8.x4.shared.b16 {%0,%1,%2,%3}, [%4];" \
        : "=r"(r0), "=r"(r1), "=r"(r2), "=r"(r3) : "r"(addr))

#define SCALE_Q 0.18033688011112042f      // 0.125 * log2(e)
#define ROWB 144

// ---------------- merged glue: W_eff folds (fp16) + x rounding, one launch -----------
struct PrepArgs {
    const float* w[4]; const float* l1[4]; const float* l2[4]; __half* out[4];
    const float4* x; uint2* xr;
};
__global__ void prep_kernel(PrepArgs a) {
    if (blockIdx.x < 4*4096) {                 // W_eff = fp16(W + l2@l1)
        int wi  = blockIdx.x >> 12;
        int idx = ((blockIdx.x & 4095) << 8) + threadIdx.x;
        int n = idx >> 10, k = idx & 1023;
        const float* l1 = a.l1[wi];
        const float* l2 = a.l2[wi];
        float acc = a.w[wi][idx];
#pragma unroll
        for (int r = 0; r < Rr; r++) acc += l2[n*Rr + r] * l1[r*Dd + k];
        a.out[wi][idx] = __float2half(acc);
    } else {                                   // x -> fp16
        int i = (blockIdx.x - 4*4096) * 256 + threadIdx.x;
        float4 v = a.x[i];
        a.xr[i] = make_uint2(h2u(__floats2half2_rn(v.x, v.y)), h2u(__floats2half2_rn(v.z, v.w)));
    }
}

// ---------------- GEMM tiling: BM=64, BN=128, warp tile 32x32, 3 CTAs/SM --------------
#define BM 64
#define BN 128
#define HBK 64
#define ABYT (BM*ROWB)                    // 9216
#define BBYT (BN*ROWB)                    // 18432
#define GSTG2 (ABYT+BBYT)                 // 27648 per stage
#define GEMM_SMEM (2*GSTG2)               // 55296 -> 3 CTAs/SM
#define NCH (Dd/HBK)                      // 16

#define HLOAD(CH, Ap, Wp) do {                                              \
        uint32_t _stg = sm_sh + (uint32_t)((CH) & 1) * GSTG2;               \
        _Pragma("unroll")                                                   \
        for (int _j = 0; _j < 2; _j++) {                                    \
            int _cl = tid + 256*_j;                                         \
            int _row = _cl >> 3, _seg = _cl & 7;                            \
            CP16(_stg + (uint32_t)(_row*ROWB + _seg*16),                    \
                 (Ap) + (size_t)(bm + _row)*Dd + (CH)*HBK + _seg*8);        \
        }                                                                   \
        _Pragma("unroll")                                                   \
        for (int _j = 0; _j < 4; _j++) {                                    \
            int _cl = tid + 256*_j;                                         \
            int _row = _cl >> 3, _seg = _cl & 7;                            \
            CP16(_stg + ABYT + (uint32_t)(_row*ROWB + _seg*16),             \
                 (Wp) + (size_t)(bn + _row)*Dd + (CH)*HBK + _seg*8);        \
        }                                                                   \
        asm volatile("cp.async.commit_group;");                             \
    } while (0)

// 2-stage, single-barrier, correct protocol:
//   wait_group 0 (stage `it` fully landed) -> barrier (all warps done reading
//   the OTHER stage at it-1) -> prefetch it+1 into the other stage -> compute it.
#define GEMM_MAINLOOP(Ap, Wp)                                               \
    HLOAD(0, Ap, Wp);                                                       \
    for (int it = 0; it < NCH; it++) {                                      \
        asm volatile("cp.async.wait_group 0;");                             \
        __syncthreads();                                                    \
        if (it + 1 < NCH) HLOAD(it + 1, Ap, Wp);                            \
        uint32_t stg = sm_sh + (uint32_t)(it & 1) * GSTG2;                  \
        uint32_t aA = stg + (uint32_t)wm*ROWB + laneoff;                    \
        uint32_t aB = stg + ABYT + (uint32_t)wn*ROWB + laneoff;             \
        _Pragma("unroll")                                                   \
        for (int kk = 0; kk < 4; kk++) {                                    \
            uint32_t af[2][4], bf[4][2];                                    \
            LDSM4(af[0][0], af[0][1], af[0][2], af[0][3], aA + kk*32);      \
            LDSM4(af[1][0], af[1][1], af[1][2], af[1][3], aA + 16*ROWB + kk*32); \
            _Pragma("unroll")                                               \
            for (int p = 0; p < 2; p++) {                                   \
                uint32_t r0, r1, r2, r3;                                    \
                LDSM4(r0, r1, r2, r3, aB + p*16*ROWB + kk*32);              \
                bf[2*p][0] = r0; bf[2*p+1][0] = r1;                         \
                bf[2*p][1] = r2; bf[2*p+1][1] = r3;                         \
            }                                                               \
            _Pragma("unroll")                                               \
            for (int mi = 0; mi < 2; mi++)                                  \
                _Pragma("unroll")                                           \
                for (int ni = 0; ni < 4; ni++)                              \
                    MMA_F16(acc[mi][ni], af[mi], bf[ni][0], bf[ni][1]);     \
        }                                                                   \
    }

// ---------------- merged Q/K/V projection kernel (blockIdx.z selects) ----------------
__global__ __launch_bounds__(256, 3) void qkv_gemm_kernel(
    const __half* __restrict__ X,
    const __half* __restrict__ Wq, const __half* __restrict__ Wk, const __half* __restrict__ Wv,
    const float* __restrict__ wqb,
    __half* __restrict__ Qh, __half* __restrict__ Kh, __half* __restrict__ Vt,
    const float* __restrict__ fc, const float* __restrict__ fs)
{
    extern __shared__ char smc[];
    uint32_t sm_sh;
    asm("{ .reg .u64 t; cvta.to.shared.u64 t, %1; cvt.u32.u64 %0, t; }" : "=r"(sm_sh) : "l"(smc));

    const int tid  = threadIdx.x;
    const int bm   = blockIdx.y * BM;
    const int bn   = blockIdx.x * BN;
    const int z    = blockIdx.z;              // 0=Q, 1=K, 2=V
    const int warp = tid >> 5, lane = tid & 31;
    const int g = lane >> 2;
    const int q = lane & 3;
    const int wm = (warp >> 2) * 32;          // 2 warp-rows
    const int wn = (warp & 3) * 32;           // 4 warp-cols
    const uint32_t laneoff = (uint32_t)((lane & 15) * ROWB + ((lane >> 4) << 4));

    const __half* W = (z == 0) ? Wq : (z == 1) ? Wk : Wv;
    float acc[2][4][4] = {};

    GEMM_MAINLOOP(X, W)

    if (z < 2) {          // Q or K: RoPE (+bias,+scale for Q) -> fp16
#pragma unroll
        for (int mi = 0; mi < 2; mi++) {
            int r0 = bm + wm + mi*16 + g;
            int s0 = r0 & (Ss-1), s1 = (r0+8) & (Ss-1);
            __half* Ph = (z == 0) ? Qh : Kh;
#pragma unroll
            for (int ni = 0; ni < 4; ni++) {
                int cn = bn + wn + ni*8 + q*2;
                int p = (cn & 63) >> 1;
                float b0 = 0.f, b1 = 0.f;
                if (z == 0) { b0 = wqb[cn]; b1 = wqb[cn+1]; }
                float c0 = fc[s0*32+p], n0 = fs[s0*32+p];
                float c1 = fc[s1*32+p], n1 = fs[s1*32+p];
                float e0 = acc[mi][ni][0]+b0, o0 = acc[mi][ni][1]+b1;
                float e1 = acc[mi][ni][2]+b0, o1 = acc[mi][ni][3]+b1;
                float re0 = e0*c0 - o0*n0, im0 = e0*n0 + o0*c0;
                float re1 = e1*c1 - o1*n1, im1 = e1*n1 + o1*c1;
                if (z == 0) { re0 *= SCALE_Q; im0 *= SCALE_Q; re1 *= SCALE_Q; im1 *= SCALE_Q; }
                *(__half2*)&Ph[(size_t)r0    *Dd + cn] = __floats2half2_rn(re0, im0);
                *(__half2*)&Ph[(size_t)(r0+8)*Dd + cn] = __floats2half2_rn(re1, im1);
            }
        }
    } else {              // V: transposed fp16
#pragma unroll
        for (int mi = 0; mi < 2; mi++) {
            int r0 = bm + wm + mi*16 + g;
            int sl = r0 & (Ss-1);
            size_t bb = (size_t)(r0 >> 12);
#pragma unroll
            for (int ni = 0; ni < 4; ni++) {
                int cn = bn + wn + ni*8 + q*2;
                int hh = cn >> 6, dd = cn & 63;
                size_t vb = ((bb*Hh + hh)*HDh + dd) * (size_t)Ss;
                Vt[vb      + sl    ] = __float2half(acc[mi][ni][0]);
                Vt[vb + Ss + sl    ] = __float2half(acc[mi][ni][1]);
                Vt[vb      + sl + 8] = __float2half(acc[mi][ni][2]);
                Vt[vb + Ss + sl + 8] = __float2half(acc[mi][ni][3]);
            }
        }
    }
}

// ---------------- output projection kernel (fp32 + bias into d_out) ------------------
__global__ __launch_bounds__(256, 3) void oproj_gemm_kernel(
    const __half* __restrict__ A, const __half* __restrict__ W,
    const float* __restrict__ bias, float* __restrict__ C)
{
    extern __shared__ char smc[];
    uint32_t sm_sh;
    asm("{ .reg .u64 t; cvta.to.shared.u64 t, %1; cvt.u32.u64 %0, t; }" : "=r"(sm_sh) : "l"(smc));

    const int tid  = threadIdx.x;
    const int bm   = blockIdx.y * BM;
    const int bn   = blockIdx.x * BN;
    const int warp = tid >> 5, lane = tid & 31;
    const int g = lane >> 2;
    const int q = lane & 3;
    const int wm = (warp >> 2) * 32;
    const int wn = (warp & 3) * 32;
    const uint32_t laneoff = (uint32_t)((lane & 15) * ROWB + ((lane >> 4) << 4));

    float acc[2][4][4] = {};

    GEMM_MAINLOOP(A, W)

#pragma unroll
    for (int mi = 0; mi < 2; mi++) {
        int r0 = bm + wm + mi*16 + g;
#pragma unroll
        for (int ni = 0; ni < 4; ni++) {
            int cn = bn + wn + ni*8 + q*2;
            float b0 = bias[cn], b1 = bias[cn+1];
            *(float2*)&C[(size_t)r0     *Dd + cn] = make_float2(acc[mi][ni][0]+b0, acc[mi][ni][1]+b1);
            *(float2*)&C[(size_t)(r0+8) *Dd + cn] = make_float2(acc[mi][ni][2]+b0, acc[mi][ni][3]+b1);
        }
    }
}

// ---------------- FP16 flash attention (round-10 exact) -------------------------------
#define AQ 128
#define AK 64
#define KPL (AK*ROWB)                     // 9216 per 64x64-half plane
#define STG_BYTES (2*KPL)                 // Kh + V = 18432 per stage
#define ASTAGES 4
#define OFF_Q (ASTAGES*STG_BYTES)         // 73728
#define ATTN_SMEM (OFF_Q + AQ*ROWB)       // +18432 = 92160

__global__ __launch_bounds__(256) void attn_mma_kernel(
    const __half* __restrict__ Qh, const __half* __restrict__ Kh,
    const __half* __restrict__ Vt, __half* __restrict__ O)
{
    extern __shared__ char smc[];
    uint32_t sm_sh;
    asm("{ .reg .u64 t; cvta.to.shared.u64 t, %1; cvt.u32.u64 %0, t; }" : "=r"(sm_sh) : "l"(smc));
    __half* sQ = (__half*)(smc + OFF_Q);

    const int tid = threadIdx.x;
    const int warp = tid >> 5, lane = tid & 31;
    const int g = lane >> 2, q = lane & 3;
    const int qt = 31 - blockIdx.x;          // heavy tiles first
    const int bh = blockIdx.y;
    const int b = bh >> 4, h = bh & 15;
    const size_t headoff = (size_t)b * Ss * Dd + (size_t)h * HDh;
    const size_t vhead = (size_t)bh * HDh * Ss;
    const int w16 = warp * 16;
    const uint32_t laneoff = (uint32_t)((lane & 15) * ROWB + ((lane >> 4) << 4));

    // ---- stage Q into smem, pull fragments via ldmatrix ----
    {
        const int r = tid >> 1, half = tid & 1;
        const __half* src = Qh + headoff + (size_t)(qt*AQ + r)*Dd + half*32;
        uint4* dst = (uint4*)(sQ + r*72 + half*32);
#pragma unroll
        for (int i = 0; i < 4; i++) dst[i] = ((const uint4*)src)[i];
    }
    __syncthreads();

    uint32_t aQ[4][4];
    {
        uint32_t qb = sm_sh + OFF_Q + (uint32_t)w16*ROWB + laneoff;
#pragma unroll
        for (int s = 0; s < 4; s++)
            LDSM4(aQ[s][0], aQ[s][1], aQ[s][2], aQ[s][3], qb + s*32);
    }

#define APREFETCH(KT) do {                                                          \
        uint32_t _stg = sm_sh + (uint32_t)((KT) % ASTAGES) * STG_BYTES;             \
        int _pl = tid >> 7;                 /* 0: K plane, 1: V plane */            \
        int _r = (tid & 127) >> 1;                                                  \
        int _half = tid & 1;                                                        \
        const __half* _gs;                                                          \
        if (_pl == 0) _gs = Kh + headoff + (size_t)((KT)*AK + _r)*Dd + _half*32;    \
        else          _gs = Vt + vhead + (size_t)_r*Ss + (KT)*AK + _half*32;        \
        uint32_t _dst = _stg + (_pl ? KPL : 0) + (uint32_t)(_r*ROWB + _half*64);    \
        _Pragma("unroll")                                                           \
        for (int _i = 0; _i < 4; _i++)                                              \
            CP16(_dst + _i*16, (const char*)_gs + _i*16);                           \
        asm volatile("cp.async.commit_group;");                                     \
    } while (0)

    float accO[8][4] = {};
    float m0 = -1e30f, m1 = -1e30f, l0 = 0.f, l1 = 0.f;   // l0,l1: per-lane partials
    const int nkt = 2*qt + 2;

    APREFETCH(0);
    APREFETCH(1);
    if (2 < nkt) APREFETCH(2);

    for (int kt = 0; kt < nkt; kt++) {
        if (kt + 3 <= nkt)      asm volatile("cp.async.wait_group 2;");
        else if (kt + 2 == nkt) asm volatile("cp.async.wait_group 1;");
        else                    asm volatile("cp.async.wait_group 0;");
        __syncthreads();
        if (kt + 3 < nkt) APREFETCH(kt + 3);

        uint32_t stg = sm_sh + (uint32_t)(kt % ASTAGES) * STG_BYTES;
        uint32_t aK = stg + laneoff;
        uint32_t aV = aK + KPL;

        // S = q @ k^T  (Q pre-scaled by 0.125*log2e -> S in log2 domain)
        float S[8][4] = {};
#pragma unroll
        for (int s = 0; s < 4; s++) {
            uint32_t bk[8][2];
#pragma unroll
            for (int p = 0; p < 4; p++) {
                uint32_t r0, r1, r2, r3;
                LDSM4(r0, r1, r2, r3, aK + p*16*ROWB + s*32);
                bk[2*p][0] = r0; bk[2*p+1][0] = r1; bk[2*p][1] = r2; bk[2*p+1][1] = r3;
            }
#pragma unroll
            for (int ni = 0; ni < 8; ni++)
                MMA_F16(S[ni], aQ[s], bk[ni][0], bk[ni][1]);
        }

        // hoist V fragments for s=0 — independent of softmax, drains during MUFU work
        uint32_t bv0[8][2];
#pragma unroll
        for (int p = 0; p < 4; p++) {
            uint32_t r0, r1, r2, r3;
            LDSM4(r0, r1, r2, r3, aV + p*16*ROWB);
            bv0[2*p][0] = r0; bv0[2*p+1][0] = r1; bv0[2*p][1] = r2; bv0[2*p+1][1] = r3;
        }

        // causal mask (only the last two tiles touch the diagonal)
        if (kt >= 2*qt) {
            const int r0g = qt*AQ + w16 + g, r1g = r0g + 8;
#pragma unroll
            for (int ni = 0; ni < 8; ni++) {
                int c = kt*AK + ni*8 + 2*q;
                if (c     > r0g) S[ni][0] = -1e30f;
                if (c + 1 > r0g) S[ni][1] = -1e30f;
                if (c     > r1g) S[ni][2] = -1e30f;
                if (c + 1 > r1g) S[ni][3] = -1e30f;
            }
        }

        // online softmax in log2 domain (l kept as per-lane partials)
        float mx0 = -1e30f, mx1 = -1e30f;
#pragma unroll
        for (int ni = 0; ni < 8; ni++) {
            mx0 = fmaxf(mx0, fmaxf(S[ni][0], S[ni][1]));
            mx1 = fmaxf(mx1, fmaxf(S[ni][2], S[ni][3]));
        }
        mx0 = fmaxf(mx0, __shfl_xor_sync(0xffffffffu, mx0, 1));
        mx0 = fmaxf(mx0, __shfl_xor_sync(0xffffffffu, mx0, 2));
        mx1 = fmaxf(mx1, __shfl_xor_sync(0xffffffffu, mx1, 1));
        mx1 = fmaxf(mx1, __shfl_xor_sync(0xffffffffu, mx1, 2));
        float mn0 = fmaxf(m0, mx0), mn1 = fmaxf(m1, mx1);
        if (__any_sync(0xffffffffu, (mn0 > m0) || (mn1 > m1))) {
            float cr0 = ex2f(m0 - mn0), cr1 = ex2f(m1 - mn1);
            m0 = mn0; m1 = mn1;
            l0 *= cr0; l1 *= cr1;
#pragma unroll
            for (int ni = 0; ni < 8; ni++) {
                accO[ni][0] *= cr0; accO[ni][1] *= cr0;
                accO[ni][2] *= cr1; accO[ni][3] *= cr1;
            }
        }
#pragma unroll
        for (int ni = 0; ni < 8; ni++) {
            S[ni][0] = ex2f(S[ni][0] - m0);
            S[ni][1] = ex2f(S[ni][1] - m0);
            S[ni][2] = ex2f(S[ni][2] - m1);
            S[ni][3] = ex2f(S[ni][3] - m1);
            l0 += S[ni][0] + S[ni][1];
            l1 += S[ni][2] + S[ni][3];
        }

        // O += P @ V  — P taken directly from S registers (C-frag == A-frag layout)
#pragma unroll
        for (int s = 0; s < 4; s++) {
            uint32_t ap[4];
            ap[0] = h2u(__floats2half2_rn(S[2*s  ][0], S[2*s  ][1]));
            ap[1] = h2u(__floats2half2_rn(S[2*s  ][2], S[2*s  ][3]));
            ap[2] = h2u(__floats2half2_rn(S[2*s+1][0], S[2*s+1][1]));
            ap[3] = h2u(__floats2half2_rn(S[2*s+1][2], S[2*s+1][3]));
            if (s == 0) {
#pragma unroll
                for (int ni = 0; ni < 8; ni++)
                    MMA_F16(accO[ni], ap, bv0[ni][0], bv0[ni][1]);
            } else {
                uint32_t bv[8][2];
#pragma unroll
                for (int p = 0; p < 4; p++) {
                    uint32_t r0, r1, r2, r3;
                    LDSM4(r0, r1, r2, r3, aV + p*16*ROWB + s*32);
                    bv[2*p][0] = r0; bv[2*p+1][0] = r1; bv[2*p][1] = r2; bv[2*p+1][1] = r3;
                }
#pragma unroll
                for (int ni = 0; ni < 8; ni++)
                    MMA_F16(accO[ni], ap, bv[ni][0], bv[ni][1]);
            }
        }
    }
#undef APREFETCH

    // epilogue: reduce l partials across the quad, normalize, store fp16
    l0 += __shfl_xor_sync(0xffffffffu, l0, 1);
    l0 += __shfl_xor_sync(0xffffffffu, l0, 2);
    l1 += __shfl_xor_sync(0xffffffffu, l1, 1);
    l1 += __shfl_xor_sync(0xffffffffu, l1, 2);
    float inv0 = 1.f / l0, inv1 = 1.f / l1;
    size_t base0 = headoff + (size_t)(qt*AQ + w16 + g) * Dd;
    size_t base1 = base0 + (size_t)8 * Dd;
#pragma unroll
    for (int ni = 0; ni < 8; ni++) {
        int c = ni*8 + 2*q;
        *(__half2*)&O[base0 + c] = __floats2half2_rn(accO[ni][0]*inv0, accO[ni][1]*inv0);
        *(__half2*)&O[base1 + c] = __floats2half2_rn(accO[ni][2]*inv1, accO[ni][3]*inv1);
    }
}

// ---------------- launch -------------------------------------------------------------
extern "C" void kernel_launch(void* const* d_in, const int* in_sizes, int n_in,
                              void* d_out, int out_size) {
    const float* x   = (const float*)d_in[0];
    const float* fc  = (const float*)d_in[1];
    const float* fs  = (const float*)d_in[2];
    const float* wq  = (const float*)d_in[4];
    const float* wqb = (const float*)d_in[5];
    const float* wk  = (const float*)d_in[6];
    const float* wv  = (const float*)d_in[7];
    const float* wo  = (const float*)d_in[8];
    const float* wob = (const float*)d_in[9];

    __half *Wq, *Wk, *Wv, *Wo, *Xr, *Qhp, *Khp, *Vtp, *AO;
    cudaGetSymbolAddress((void**)&Wq, g_Wq);
    cudaGetSymbolAddress((void**)&Wk, g_Wk);
    cudaGetSymbolAddress((void**)&Wv, g_Wv);
    cudaGetSymbolAddress((void**)&Wo, g_Wo);
    cudaGetSymbolAddress((void**)&Xr, g_X);
    cudaGetSymbolAddress((void**)&Qhp, g_Qh);
    cudaGetSymbolAddress((void**)&Khp, g_Kh);
    cudaGetSymbolAddress((void**)&Vtp, g_Vt);
    cudaGetSymbolAddress((void**)&AO, g_AO);

    cudaFuncSetAttribute(qkv_gemm_kernel, cudaFuncAttributeMaxDynamicSharedMemorySize, GEMM_SMEM);
    cudaFuncSetAttribute(oproj_gemm_kernel, cudaFuncAttributeMaxDynamicSharedMemorySize, GEMM_SMEM);
    cudaFuncSetAttribute(attn_mma_kernel, cudaFuncAttributeMaxDynamicSharedMemorySize, ATTN_SMEM);

    // 1. Glue: fold LoRA into 4 weights + round x, single launch
    PrepArgs pa;
    pa.w[0]=wq; pa.l1[0]=(const float*)d_in[10]; pa.l2[0]=(const float*)d_in[11]; pa.out[0]=Wq;
    pa.w[1]=wk; pa.l1[1]=(const float*)d_in[12]; pa.l2[1]=(const float*)d_in[13]; pa.out[1]=Wk;
    pa.w[2]=wv; pa.l1[2]=(const float*)d_in[14]; pa.l2[2]=(const float*)d_in[15]; pa.out[2]=Wv;
    pa.w[3]=wo; pa.l1[3]=(const float*)d_in[16]; pa.l2[3]=(const float*)d_in[17]; pa.out[3]=Wo;
    pa.x = (const float4*)x; pa.xr = (uint2*)Xr;
    prep_kernel<<<4*4096 + (Mm*Dd/4)/256, 256>>>(pa);

    // 2. Q/K/V projections in ONE launch (z selects weight + epilogue), 3 CTAs/SM
    dim3 gq(Dd/BN, Mm/BM, 3);
    qkv_gemm_kernel<<<gq, 256, GEMM_SMEM>>>(Xr, Wq, Wk, Wv, wqb, Qhp, Khp, Vtp, fc, fs);

    // 3. FP16 flash attention (round-10 config)
    dim3 ga(Ss/AQ, Bb*Hh);
    attn_mma_kernel<<<ga, 256, ATTN_SMEM>>>(Qhp, Khp, Vtp, AO);

    // 4. Output projection into d_out (fp32 + bias)
    dim3 gg(Dd/BN, Mm/BM);
    oproj_gemm_kernel<<<gg, 256, GEMM_SMEM>>>(AO, Wo, wob, (float*)d_out);
}